// round 3
// baseline (speedup 1.0000x reference)
#include <cuda_runtime.h>

// Correlation1dCost: feat [B,C,H,W] f32 -> out [B,D,H,W] f32
// out[b,d,y,x] = leakyrelu( sum_c f1[b,c,y,x] * f2[b,c,y,x+d-47] ), 0.1 slope
#define B_ 8
#define C_ 128
#define H_ 128
#define W_ 256
#define D_ 48
#define PAD_ 47

#define CK 16          // channels per smem chunk
#define S2W 303        // valid window width (47 pad + 256)
#define S2P 304        // padded row (16B-aligned stride: 304*4=1216)

typedef unsigned long long u64;

#define PACK2(o, lo, hi) asm("mov.b64 %0, {%1, %2};" : "=l"(o) : "f"(lo), "f"(hi))
#define UNPACK2(lo, hi, i) asm("mov.b64 {%0, %1}, %2;" : "=f"(lo), "=f"(hi) : "l"(i))
#define FMA2(acc, a, b) asm("fma.rn.f32x2 %0, %1, %2, %0;" : "+l"(acc) : "l"(a), "l"(b))

__global__ __launch_bounds__(128, 2)
void corr1d_kernel(const float* __restrict__ f1,
                   const float* __restrict__ f2,
                   float* __restrict__ out) {
    __shared__ float s1[CK][W_];    // feat1 row chunk
    __shared__ float s2[CK][S2P];   // feat2 window: s2[k] = f2[x = k-47], zero OOB

    const int tid = threadIdx.x;
    const int b   = blockIdx.x >> 7;     // blockIdx.x = b*H + y
    const int y   = blockIdx.x & (H_ - 1);

    // 128 threads: tx in [0,32) -> 8 x each (x = tx*8 .. +7)
    //              td in [0,4)  -> 12 d each (d = td*12 .. +11)
    const int tx = tid >> 2;
    const int td = tid & 3;
    const int xb = tx * 8;
    const int db = td * 12;

    const int HW = H_ * W_;
    const float* f1p = f1 + (b * C_ * H_ + y) * W_;  // + c*HW + x
    const float* f2p = f2 + (b * C_ * H_ + y) * W_;  // + c*HW + x

    // acc[m][j]: packed pair ( out[xb+2m, db+j], out[xb+2m+1, db+j] )
    u64 acc[4][12];
#pragma unroll
    for (int m = 0; m < 4; ++m)
#pragma unroll
        for (int j = 0; j < 12; ++j) acc[m][j] = 0ull;

    for (int c0 = 0; c0 < C_; c0 += CK) {
        __syncthreads();
        // ---- load chunk: feat1 row (256 f) + feat2 window (303 f) per channel
#pragma unroll
        for (int c = 0; c < CK; ++c) {
            const float* p1 = f1p + (c0 + c) * HW;
            *reinterpret_cast<float2*>(&s1[c][2 * tid]) =
                *reinterpret_cast<const float2*>(p1 + 2 * tid);

            const float* p2 = f2p + (c0 + c) * HW - PAD_;  // p2[k] = f2[k-47]
            s2[c][tid] = (tid >= PAD_) ? p2[tid] : 0.0f;
            s2[c][tid + 128] = p2[tid + 128];               // k in [128,256): valid
            if (tid < 48)                                    // k in [256,304)
                s2[c][tid + 256] = (tid < 47) ? p2[tid + 256] : 0.0f;
        }
        __syncthreads();

        // ---- compute
#pragma unroll
        for (int c = 0; c < CK; ++c) {
            // feat1 pairs (free out of LDS.128 quads)
            float4 A0 = *reinterpret_cast<const float4*>(&s1[c][xb]);
            float4 A1 = *reinterpret_cast<const float4*>(&s1[c][xb + 4]);
            u64 pa[4];
            PACK2(pa[0], A0.x, A0.y); PACK2(pa[1], A0.z, A0.w);
            PACK2(pa[2], A1.x, A1.y); PACK2(pa[3], A1.z, A1.w);

            // feat2 window w[0..18] = s2[c][xb+db .. +18], via 5 LDS.128
            const float* wp = &s2[c][xb + db];   // multiple of 4 floats -> 16B aligned
            float w[20];
#pragma unroll
            for (int q = 0; q < 5; ++q) {
                float4 v = *reinterpret_cast<const float4*>(wp + 4 * q);
                w[4 * q] = v.x; w[4 * q + 1] = v.y;
                w[4 * q + 2] = v.z; w[4 * q + 3] = v.w;
            }
            // sliding pairs pr[k] = (w[k], w[k+1]), k = 2m+j in [0,17]
            u64 pr[18];
#pragma unroll
            for (int k = 0; k < 18; ++k) PACK2(pr[k], w[k], w[k + 1]);

#pragma unroll
            for (int m = 0; m < 4; ++m)
#pragma unroll
                for (int j = 0; j < 12; ++j)
                    FMA2(acc[m][j], pa[m], pr[2 * m + j]);
        }
    }

    // ---- epilogue: leaky relu + coalesced float4 stores
#pragma unroll
    for (int j = 0; j < 12; ++j) {
        const int d = db + j;
        float v[8];
#pragma unroll
        for (int m = 0; m < 4; ++m) {
            float lo, hi;
            UNPACK2(lo, hi, acc[m][j]);
            v[2 * m]     = fmaxf(lo, 0.1f * lo);
            v[2 * m + 1] = fmaxf(hi, 0.1f * hi);
        }
        float* op = out + ((b * D_ + d) * H_ + y) * W_ + xb;
        *reinterpret_cast<float4*>(op)     = make_float4(v[0], v[1], v[2], v[3]);
        *reinterpret_cast<float4*>(op + 4) = make_float4(v[4], v[5], v[6], v[7]);
    }
}

extern "C" void kernel_launch(void* const* d_in, const int* in_sizes, int n_in,
                              void* d_out, int out_size) {
    (void)in_sizes; (void)n_in; (void)out_size;
    const float* f1 = (const float*)d_in[0];
    const float* f2 = (const float*)d_in[1];
    float* out = (float*)d_out;

    corr1d_kernel<<<B_ * H_, 128>>>(f1, f2, out);
}

// round 4
// speedup vs baseline: 1.4318x; 1.4318x over previous
#include <cuda_runtime.h>

// Correlation1dCost: feat [B,C,H,W] f32 -> out [B,D,H,W] f32
// out[b,d,y,x] = leakyrelu_0.1( sum_c f1[b,c,y,x] * f2[b,c,y,x+d-47] ), zero OOB
#define B_ 8
#define C_ 128
#define H_ 128
#define W_ 256
#define D_ 48

#define CK 8          // channels per smem chunk
#define S1S 256       // s1 row stride (words)
#define S2S 304       // s2 row stride (words): [0..46]=zeros, [47..302]=f2 row
#define NT 192        // 6 warps: warp = d-group, lane = x-chunk

// XOR swizzle: flips quad-bit 2 based on 32-word-segment parity.
// Preserves 16B quads; stays inside the 32-word segment; makes all compute
// LDS.128 patterns {8*lane + s, s mult of 4} conflict-free.
__device__ __forceinline__ int swz(int k) { return k ^ (((k >> 5) & 1) << 2); }
__device__ __forceinline__ float lrelu(float v) { return fmaxf(v, 0.1f * v); }

__global__ __launch_bounds__(NT)
void corr1d_kernel(const float* __restrict__ f1,
                   const float* __restrict__ f2,
                   float* __restrict__ out) {
    __shared__ __align__(16) float s1[CK][S1S];
    __shared__ __align__(16) float s2[CK][S2S];

    const int tid  = threadIdx.x;
    const int b    = blockIdx.x >> 7;          // blockIdx.x = b*H + y
    const int y    = blockIdx.x & (H_ - 1);
    const int lane = tid & 31;
    const int wrp  = tid >> 5;                 // 0..5
    const int xb   = lane * 8;                 // x base: 8 x's per thread
    const int db   = wrp * 8;                  // d base: 8 d's per thread

    const int HW = H_ * W_;
    const float* f1p = f1 + (b * C_ * H_ + y) * W_;
    const float* f2p = f2 + (b * C_ * H_ + y) * W_;

    // Zero the left pad (phys words swz([0,47)) per row) ONCE.
    // Chunk fills only write swz([47,303)) — disjoint, so pads stay zero.
    for (int i = tid; i < CK * 47; i += NT) {
        int c = i / 47, k = i - c * 47;
        s2[c][swz(k)] = 0.0f;
    }

    float acc[8][8];
#pragma unroll
    for (int i = 0; i < 8; ++i)
#pragma unroll
        for (int j = 0; j < 8; ++j) acc[i][j] = 0.0f;

    for (int c0 = 0; c0 < C_; c0 += CK) {
        __syncthreads();
        // fill feat1 rows (coalesced LDG, near-conflict-free STS)
        for (int j = tid; j < CK * W_; j += NT) {
            int c = j >> 8, x = j & (W_ - 1);
            s1[c][swz(x)] = f1p[(c0 + c) * HW + x];
        }
        // fill feat2 rows at phys offset +47 (zero pad untouched)
        for (int j = tid; j < CK * W_; j += NT) {
            int c = j >> 8, x = j & (W_ - 1);
            s2[c][swz(47 + x)] = f2p[(c0 + c) * HW + x];
        }
        __syncthreads();

#pragma unroll
        for (int c = 0; c < CK; ++c) {
            // feat1: 8 x-values, two conflict-free LDS.128
            float a[8];
            {
                float4 v0 = *reinterpret_cast<const float4*>(&s1[c][swz(xb)]);
                float4 v1 = *reinterpret_cast<const float4*>(&s1[c][swz(xb + 4)]);
                a[0] = v0.x; a[1] = v0.y; a[2] = v0.z; a[3] = v0.w;
                a[4] = v1.x; a[5] = v1.y; a[6] = v1.z; a[7] = v1.w;
            }
            // feat2 window: w[t] = s2phys[xb+db+t] = f2[xb+db+t-47], t in [0,16)
            // (xb+db multiple of 8 -> aligned quads; all four conflict-free)
            float w[16];
#pragma unroll
            for (int q = 0; q < 4; ++q) {
                float4 u = *reinterpret_cast<const float4*>(&s2[c][swz(xb + db + 4 * q)]);
                w[4 * q] = u.x; w[4 * q + 1] = u.y;
                w[4 * q + 2] = u.z; w[4 * q + 3] = u.w;
            }
            // out[x=xb+i, d=db+j] += a[i] * w[i+j]
#pragma unroll
            for (int i = 0; i < 8; ++i)
#pragma unroll
                for (int j = 0; j < 8; ++j)
                    acc[i][j] = fmaf(a[i], w[i + j], acc[i][j]);
        }
    }

    // epilogue: leaky relu + coalesced float4 stores (lane-consecutive x)
#pragma unroll
    for (int j = 0; j < 8; ++j) {
        const int d = db + j;
        float* op = out + ((b * D_ + d) * H_ + y) * W_ + xb;
        float4 o0, o1;
        o0.x = lrelu(acc[0][j]); o0.y = lrelu(acc[1][j]);
        o0.z = lrelu(acc[2][j]); o0.w = lrelu(acc[3][j]);
        o1.x = lrelu(acc[4][j]); o1.y = lrelu(acc[5][j]);
        o1.z = lrelu(acc[6][j]); o1.w = lrelu(acc[7][j]);
        *reinterpret_cast<float4*>(op)     = o0;
        *reinterpret_cast<float4*>(op + 4) = o1;
    }
}

extern "C" void kernel_launch(void* const* d_in, const int* in_sizes, int n_in,
                              void* d_out, int out_size) {
    (void)in_sizes; (void)n_in; (void)out_size;
    const float* f1 = (const float*)d_in[0];
    const float* f2 = (const float*)d_in[1];
    float* out = (float*)d_out;

    corr1d_kernel<<<B_ * H_, NT>>>(f1, f2, out);
}

// round 5
// speedup vs baseline: 3.4756x; 2.4274x over previous
#include <cuda_runtime.h>

// Correlation1dCost: feat [B,C,H,W] f32 -> out [B,D,H,W] f32
// out[b,d,y,x] = leakyrelu_0.1( sum_c f1[b,c,y,x] * f2[b,c,y,x+d-47] ), zero OOB
#define B_ 8
#define C_ 128
#define H_ 128
#define W_ 256
#define D_ 48

#define CK 8          // channels per chunk (16 chunks)
#define NCH (C_ / CK)
#define S1S 256       // s1 row stride (words)
#define S2S 304       // s2 row stride: phys[48..303] = f2[0..255], phys[0..47] = 0
#define NT 192        // 6 warps: warp = d-group, lane = x-chunk
#define HW_ (H_ * W_)

// XOR swizzle (quad-preserving): conflict-free for all compute patterns
// {8*lane + s, s mult of 4}. swz(k+r) = swz(k)+r for k mult 4, r<4.
__device__ __forceinline__ int swz(int k) { return k ^ (((k >> 5) & 1) << 2); }
__device__ __forceinline__ float lrelu(float v) { return fmaxf(v, 0.1f * v); }

__global__ __launch_bounds__(NT, 2)
void corr1d_kernel(const float* __restrict__ f1,
                   const float* __restrict__ f2,
                   float* __restrict__ out) {
    __shared__ __align__(16) float s1[2][CK][S1S];
    __shared__ __align__(16) float s2[2][CK][S2S];

    const int tid  = threadIdx.x;
    const int b    = blockIdx.x >> 7;          // blockIdx.x = b*H + y
    const int y    = blockIdx.x & (H_ - 1);
    const int lane = tid & 31;
    const int wrp  = tid >> 5;                 // 0..5
    const int xb   = lane * 8;                 // 8 x's per thread
    const int db   = wrp * 8;                  // 8 d's per thread

    const float* f1p = f1 + (b * C_ * H_ + y) * W_;
    const float* f2p = f2 + (b * C_ * H_ + y) * W_;

    // Fill-quads: x4 identical for all 3 quads/tensor (192 = 3*64, 384 = 6*64)
    const int x4  = (tid & 63) * 4;
    const int cA  = tid >> 6;                  // 0..2 -> rows cA, cA+3, cA+6
    const bool has3 = (tid < 128);             // third quad: rows 6,7 only

    // Zero the left pads of both buffers ONCE (fills never touch phys [0,48)).
    for (int i = tid; i < 2 * CK * 48; i += NT) {
        int bu = i >= CK * 48;
        int r  = bu ? i - CK * 48 : i;
        int c  = r / 48, k = r - c * 48;
        s2[bu][c][swz(k)] = 0.0f;
    }

    float acc[8][8];
#pragma unroll
    for (int i = 0; i < 8; ++i)
#pragma unroll
        for (int j = 0; j < 8; ++j) acc[i][j] = 0.0f;

    float4 ra[3], rb[3];   // in-flight fill registers

    // ---- prologue: load + store chunk 0
    {
        const float* p1 = f1p + x4;
        const float* p2 = f2p + x4;
        ra[0] = *(const float4*)(p1 + cA * HW_);
        ra[1] = *(const float4*)(p1 + (cA + 3) * HW_);
        rb[0] = *(const float4*)(p2 + cA * HW_);
        rb[1] = *(const float4*)(p2 + (cA + 3) * HW_);
        if (has3) {
            ra[2] = *(const float4*)(p1 + (cA + 6) * HW_);
            rb[2] = *(const float4*)(p2 + (cA + 6) * HW_);
        }
        *(float4*)&s1[0][cA][swz(x4)]          = ra[0];
        *(float4*)&s1[0][cA + 3][swz(x4)]      = ra[1];
        *(float4*)&s2[0][cA][swz(48 + x4)]     = rb[0];
        *(float4*)&s2[0][cA + 3][swz(48 + x4)] = rb[1];
        if (has3) {
            *(float4*)&s1[0][cA + 6][swz(x4)]      = ra[2];
            *(float4*)&s2[0][cA + 6][swz(48 + x4)] = rb[2];
        }
    }
    __syncthreads();

#pragma unroll 2
    for (int k = 0; k < NCH; ++k) {
        const int cur = k & 1;

        // ---- issue next chunk's LDGs first (latency covered by compute)
        if (k + 1 < NCH) {
            const float* p1 = f1p + (k + 1) * CK * HW_ + x4;
            const float* p2 = f2p + (k + 1) * CK * HW_ + x4;
            ra[0] = *(const float4*)(p1 + cA * HW_);
            ra[1] = *(const float4*)(p1 + (cA + 3) * HW_);
            rb[0] = *(const float4*)(p2 + cA * HW_);
            rb[1] = *(const float4*)(p2 + (cA + 3) * HW_);
            if (has3) {
                ra[2] = *(const float4*)(p1 + (cA + 6) * HW_);
                rb[2] = *(const float4*)(p2 + (cA + 6) * HW_);
            }
        }

        // ---- compute chunk k
#pragma unroll
        for (int c = 0; c < CK; ++c) {
            float a[8];
            {
                float4 v0 = *(const float4*)&s1[cur][c][swz(xb)];
                float4 v1 = *(const float4*)&s1[cur][c][swz(xb + 4)];
                a[0] = v0.x; a[1] = v0.y; a[2] = v0.z; a[3] = v0.w;
                a[4] = v1.x; a[5] = v1.y; a[6] = v1.z; a[7] = v1.w;
            }
            // window: 4 aligned quads from base xb+db; needed words [1..15)
            // wq[t] = phys[xb+db+t] ; f2[X] lives at phys X+48
            // -> a[i]*f2[xb+i+db+j-47] = a[i]*wq[i+j+1]
            float wq[16];
#pragma unroll
            for (int q = 0; q < 4; ++q) {
                float4 u = *(const float4*)&s2[cur][c][swz(xb + db + 4 * q)];
                wq[4 * q] = u.x; wq[4 * q + 1] = u.y;
                wq[4 * q + 2] = u.z; wq[4 * q + 3] = u.w;
            }
#pragma unroll
            for (int i = 0; i < 8; ++i)
#pragma unroll
                for (int j = 0; j < 8; ++j)
                    acc[i][j] = fmaf(a[i], wq[i + j + 1], acc[i][j]);
        }

        // ---- store next chunk into the other buffer
        if (k + 1 < NCH) {
            const int nxt = cur ^ 1;
            *(float4*)&s1[nxt][cA][swz(x4)]          = ra[0];
            *(float4*)&s1[nxt][cA + 3][swz(x4)]      = ra[1];
            *(float4*)&s2[nxt][cA][swz(48 + x4)]     = rb[0];
            *(float4*)&s2[nxt][cA + 3][swz(48 + x4)] = rb[1];
            if (has3) {
                *(float4*)&s1[nxt][cA + 6][swz(x4)]      = ra[2];
                *(float4*)&s2[nxt][cA + 6][swz(48 + x4)] = rb[2];
            }
        }
        __syncthreads();
    }

    // ---- epilogue: leaky relu + coalesced float4 stores
#pragma unroll
    for (int j = 0; j < 8; ++j) {
        const int d = db + j;
        float* op = out + ((b * D_ + d) * H_ + y) * W_ + xb;
        float4 o0, o1;
        o0.x = lrelu(acc[0][j]); o0.y = lrelu(acc[1][j]);
        o0.z = lrelu(acc[2][j]); o0.w = lrelu(acc[3][j]);
        o1.x = lrelu(acc[4][j]); o1.y = lrelu(acc[5][j]);
        o1.z = lrelu(acc[6][j]); o1.w = lrelu(acc[7][j]);
        *(float4*)op       = o0;
        *(float4*)(op + 4) = o1;
    }
}

extern "C" void kernel_launch(void* const* d_in, const int* in_sizes, int n_in,
                              void* d_out, int out_size) {
    (void)in_sizes; (void)n_in; (void)out_size;
    const float* f1 = (const float*)d_in[0];
    const float* f2 = (const float*)d_in[1];
    float* out = (float*)d_out;

    corr1d_kernel<<<B_ * H_, NT>>>(f1, f2, out);
}

// round 6
// speedup vs baseline: 5.0497x; 1.4529x over previous
#include <cuda_runtime.h>
#include <cstdint>

// Correlation1dCost: feat [B,C,H,W] f32 -> out [B,D,H,W] f32
// out[b,d,y,x] = leakyrelu_0.1( sum_c f1[b,c,y,x] * f2[b,c,y,x+d-47] ), zero OOB
// Band-GEMM on tensor cores: per (b,y), G = F1^T F2, out[x,d] = G[x, x+d-47].
#define B_ 8
#define C_ 128
#define H_ 128
#define W_ 256
#define D_ 48
#define HW_ (H_ * W_)

#define CK 16              // channels per chunk
#define NCH 8              // chunks
#define S1S 264            // s1 row stride (words), 264 % 32 == 8 -> conflict-free frags
#define S2S 328            // s2 row stride (words), 328 % 32 == 8
#define S2OFF 48           // left zero pad: phys col = x' + 48
#define NT 512             // 16 warps; warp w = x-rows [16w, 16w+16)
#define STG_S 260          // staging row stride (words), 16B-aligned rows

#define S1B(st) ((st) * (CK * S1S))
#define S2B(st) (2 * CK * S1S + (st) * (CK * S2S))
#define SMEM_FLOATS (2 * CK * S1S + 2 * CK * S2S)   // 18944 floats = 75776 B

extern __shared__ float smf[];

__device__ __forceinline__ uint32_t cvt_tf32(float f) {
    uint32_t u;
    asm("cvt.rna.tf32.f32 %0, %1;" : "=r"(u) : "f"(f));
    return u;
}

__device__ __forceinline__ void sts_tf32_quad(float* dst, float4 v) {
    uint4 q;
    q.x = cvt_tf32(v.x); q.y = cvt_tf32(v.y);
    q.z = cvt_tf32(v.z); q.w = cvt_tf32(v.w);
    *reinterpret_cast<uint4*>(dst) = q;
}

__device__ __forceinline__ void mma_tf32(float d[4], const uint32_t a[4],
                                         uint32_t b0, uint32_t b1) {
    asm volatile(
        "mma.sync.aligned.m16n8k8.row.col.f32.tf32.tf32.f32 "
        "{%0,%1,%2,%3}, {%4,%5,%6,%7}, {%8,%9}, {%0,%1,%2,%3};"
        : "+f"(d[0]), "+f"(d[1]), "+f"(d[2]), "+f"(d[3])
        : "r"(a[0]), "r"(a[1]), "r"(a[2]), "r"(a[3]), "r"(b0), "r"(b1));
}

__device__ __forceinline__ float lrelu(float v) { return fmaxf(v, 0.1f * v); }

__global__ __launch_bounds__(NT, 1)
void corr1d_tc(const float* __restrict__ f1,
               const float* __restrict__ f2,
               float* __restrict__ out) {
    const int tid  = threadIdx.x;
    const int b    = blockIdx.x >> 7;          // blockIdx.x = b*H + y
    const int y    = blockIdx.x & (H_ - 1);
    const int lane = tid & 31;
    const int w    = tid >> 5;                 // warp 0..15 -> x-rows [16w,16w+16)
    const int gid  = lane >> 2;                // 0..7
    const int tig  = lane & 3;                 // 0..3

    const float* f1p = f1 + (b * C_ * H_ + y) * W_;
    const float* f2p = f2 + (b * C_ * H_ + y) * W_;

    // zero left pads of s2 (both stages) ONCE; fills never touch cols [0,48)
    for (int i = tid; i < 2 * CK * S2OFF; i += NT) {
        int st = i / (CK * S2OFF);
        int r  = i % (CK * S2OFF);
        smf[S2B(st) + (r / S2OFF) * S2S + (r % S2OFF)] = 0.0f;
    }

    // fill geometry: 1024 quads per tensor per chunk, 2 per thread
    const int r0 = tid >> 6;                   // rows 0..7
    const int r1 = r0 + 8;                     // rows 8..15
    const int cq = (tid & 63) * 4;             // quad col 0..252

    // D fragments: 8 n-tiles x 4 regs
    float dA[8][4];
#pragma unroll
    for (int t = 0; t < 8; ++t)
#pragma unroll
        for (int c4 = 0; c4 < 4; ++c4) dA[t][c4] = 0.0f;

    float4 p1a, p1b, p2a, p2b;

    // prologue: chunk 0
    p1a = *(const float4*)(f1p + r0 * HW_ + cq);
    p1b = *(const float4*)(f1p + r1 * HW_ + cq);
    p2a = *(const float4*)(f2p + r0 * HW_ + cq);
    p2b = *(const float4*)(f2p + r1 * HW_ + cq);
    sts_tf32_quad(&smf[S1B(0) + r0 * S1S + cq], p1a);
    sts_tf32_quad(&smf[S1B(0) + r1 * S1S + cq], p1b);
    sts_tf32_quad(&smf[S2B(0) + r0 * S2S + S2OFF + cq], p2a);
    sts_tf32_quad(&smf[S2B(0) + r1 * S2S + S2OFF + cq], p2b);
    __syncthreads();

    for (int k = 0; k < NCH; ++k) {
        const int cur = k & 1;

        // prefetch next chunk (LDG latency covered by MMA work)
        if (k + 1 < NCH) {
            const int c0 = (k + 1) * CK;
            p1a = *(const float4*)(f1p + (c0 + r0) * HW_ + cq);
            p1b = *(const float4*)(f1p + (c0 + r1) * HW_ + cq);
            p2a = *(const float4*)(f2p + (c0 + r0) * HW_ + cq);
            p2b = *(const float4*)(f2p + (c0 + r1) * HW_ + cq);
        }

        const uint32_t* s1q = (const uint32_t*)(smf + S1B(cur));
        const uint32_t* s2q = (const uint32_t*)(smf + S2B(cur));
        const int xw = 16 * w;

        // A fragments for both k8 steps (conflict-free: stride%32==8)
        uint32_t A[2][4];
#pragma unroll
        for (int ks = 0; ks < 2; ++ks) {
            const int kr = ks * 8 + tig;
            A[ks][0] = s1q[kr * S1S + xw + gid];            // (row gid,   k tig)
            A[ks][1] = s1q[kr * S1S + xw + gid + 8];        // (row gid+8, k tig)
            A[ks][2] = s1q[(kr + 4) * S1S + xw + gid];      // (row gid,   k tig+4)
            A[ks][3] = s1q[(kr + 4) * S1S + xw + gid + 8];  // (row gid+8, k tig+4)
        }

        // 8 n-tiles: x' base = 16w + 8t - 48 -> phys col base = 16w + 8t
#pragma unroll
        for (int t = 0; t < 8; ++t) {
            const int nb = xw + 8 * t + gid;   // phys col for this lane
#pragma unroll
            for (int ks = 0; ks < 2; ++ks) {
                const int kr = ks * 8 + tig;
                uint32_t b0 = s2q[kr * S2S + nb];        // (k tig,   n gid)
                uint32_t b1 = s2q[(kr + 4) * S2S + nb];  // (k tig+4, n gid)
                mma_tf32(dA[t], A[ks], b0, b1);
            }
        }

        // store prefetched chunk into other stage
        if (k + 1 < NCH) {
            const int nxt = cur ^ 1;
            sts_tf32_quad(&smf[S1B(nxt) + r0 * S1S + cq], p1a);
            sts_tf32_quad(&smf[S1B(nxt) + r1 * S1S + cq], p1b);
            sts_tf32_quad(&smf[S2B(nxt) + r0 * S2S + S2OFF + cq], p2a);
            sts_tf32_quad(&smf[S2B(nxt) + r1 * S2S + S2OFF + cq], p2b);
        }
        __syncthreads();
    }

    // ---- epilogue: scatter band into smem staging [d][x], then coalesced out
    // tile t, reg c4: r = gid + 8*(c4>=2), cc = 2*tig + (c4&1)
    // x = 16w + r ; d = 8t + cc - r - 1   (warp-independent!)
#pragma unroll
    for (int t = 0; t < 8; ++t) {
#pragma unroll
        for (int c4 = 0; c4 < 4; ++c4) {
            const int r  = gid + ((c4 >= 2) ? 8 : 0);
            const int cc = 2 * tig + (c4 & 1);
            const int d  = 8 * t + cc - r - 1;
            if (d >= 0 && d < D_)
                smf[d * STG_S + 16 * w + r] = lrelu(dA[t][c4]);
        }
    }
    __syncthreads();

    // copy staging -> out[b, d, y, :], float4 coalesced
    // 48*256 floats = 3072 quads over 512 threads = 6 quads each
    float* ob = out + ((b * D_) * H_ + y) * W_;
#pragma unroll
    for (int s = 0; s < 6; ++s) {
        const int qid = tid + s * NT;          // 0..3071
        const int d   = qid >> 6;              // 0..47
        const int xq  = (qid & 63) * 4;        // 0..252
        float4 v = *(const float4*)(smf + d * STG_S + xq);
        *(float4*)(ob + d * HW_ + xq) = v;
    }
}

extern "C" void kernel_launch(void* const* d_in, const int* in_sizes, int n_in,
                              void* d_out, int out_size) {
    (void)in_sizes; (void)n_in; (void)out_size;
    const float* f1 = (const float*)d_in[0];
    const float* f2 = (const float*)d_in[1];
    float* out = (float*)d_out;

    cudaFuncSetAttribute(corr1d_tc, cudaFuncAttributeMaxDynamicSharedMemorySize,
                         SMEM_FLOATS * sizeof(float));
    corr1d_tc<<<B_ * H_, NT, SMEM_FLOATS * sizeof(float)>>>(f1, f2, out);
}

// round 8
// speedup vs baseline: 6.6710x; 1.3211x over previous
#include <cuda_runtime.h>
#include <cstdint>

// Correlation1dCost: feat [B,C,H,W] f32 -> out [B,D,H,W] f32
// out[b,d,y,x] = leakyrelu_0.1( sum_c f1[b,c,y,x] * f2[b,c,y,x+d-47] ), zero OOB
// Band-GEMM on tensor cores (m16n8k8 tf32), cp.async 4-stage pipeline.
#define B_ 8
#define C_ 128
#define H_ 128
#define W_ 256
#define D_ 48
#define HW_ (H_ * W_)

#define CK 8               // channels per chunk = one k8 MMA step
#define NCH 16             // chunks
#define NSTG 4             // pipeline stages
#define S1S 264            // s1 row stride (words), %32==8 -> conflict-free frags
#define S2S 328            // s2 row stride (words), %32==8
#define S2OFF 48           // left zero pad: phys col = x' + 48
#define NT 256             // 8 warps; warp w = x-rows [32w, 32w+32)
#define STG_S 260          // epilogue staging row stride

#define STAGE_W (CK * S1S + CK * S2S)          // 4736 words per stage
#define SMEM_BYTES (NSTG * STAGE_W * 4)        // 75776 B

extern __shared__ float smf[];

#define CP16(dst, src) asm volatile( \
    "cp.async.cg.shared.global [%0], [%1], 16;\n" :: "r"(dst), "l"(src))
#define CP_COMMIT() asm volatile("cp.async.commit_group;\n" ::: "memory")
#define CP_WAIT(n)  asm volatile("cp.async.wait_group %0;\n" :: "n"(n) : "memory")

__device__ __forceinline__ uint32_t cvt_tf32(uint32_t f) {
    uint32_t u;
    asm("cvt.rna.tf32.f32 %0, %1;" : "=r"(u) : "r"(f));
    return u;
}

__device__ __forceinline__ void mma_tf32(float d[4], const uint32_t a[4],
                                         uint32_t b0, uint32_t b1) {
    asm volatile(
        "mma.sync.aligned.m16n8k8.row.col.f32.tf32.tf32.f32 "
        "{%0,%1,%2,%3}, {%4,%5,%6,%7}, {%8,%9}, {%0,%1,%2,%3};"
        : "+f"(d[0]), "+f"(d[1]), "+f"(d[2]), "+f"(d[3])
        : "r"(a[0]), "r"(a[1]), "r"(a[2]), "r"(a[3]), "r"(b0), "r"(b1));
}

__device__ __forceinline__ float lrelu(float v) { return fmaxf(v, 0.1f * v); }

__global__ __launch_bounds__(NT, 2)
void corr1d_tc(const float* __restrict__ f1,
               const float* __restrict__ f2,
               float* __restrict__ out) {
    const int tid  = threadIdx.x;
    const int b    = blockIdx.x >> 7;          // blockIdx.x = b*H + y
    const int y    = blockIdx.x & (H_ - 1);
    const int lane = tid & 31;
    const int w    = tid >> 5;                 // warp 0..7 -> x in [32w, 32w+32)
    const int gid  = lane >> 2;                // 0..7
    const int tig  = lane & 3;                 // 0..3
    const int xw   = 32 * w;

    const float* f1p = f1 + (b * C_ * H_ + y) * W_;
    const float* f2p = f2 + (b * C_ * H_ + y) * W_;

    // zero s2 left pads for all stages ONCE (cp.async fills never touch them)
    for (int i = tid; i < NSTG * CK * S2OFF; i += NT) {
        int st = i / (CK * S2OFF);
        int r  = i % (CK * S2OFF);
        smf[st * STAGE_W + CK * S1S + (r / S2OFF) * S2S + (r % S2OFF)] = 0.0f;
    }

    // fill geometry: per chunk, per tensor: CK(8) rows x 256 cols = 512 quads
    // thread handles quads tid and tid+256 -> rows qr and qr+4
    const int qr = tid >> 6;                   // 0..3
    const int qc = (tid & 63) * 4;             // 0..252
    const uint32_t smem_base = (uint32_t)__cvta_generic_to_shared(smf);

    // issue one chunk's cp.asyncs
    auto issue = [&](int k) {
        const int st = k & (NSTG - 1);
        const int c0 = k * CK;
        const uint32_t s1b = smem_base + (st * STAGE_W) * 4;
        const uint32_t s2b = s1b + (CK * S1S) * 4;
        CP16(s1b + (qr * S1S + qc) * 4,             f1p + (c0 + qr) * HW_ + qc);
        CP16(s1b + ((qr + 4) * S1S + qc) * 4,       f1p + (c0 + qr + 4) * HW_ + qc);
        CP16(s2b + (qr * S2S + S2OFF + qc) * 4,     f2p + (c0 + qr) * HW_ + qc);
        CP16(s2b + ((qr + 4) * S2S + S2OFF + qc) * 4, f2p + (c0 + qr + 4) * HW_ + qc);
    };

    // D fragments: frag[i][u] = m-tile i (x base 32w+16i), band tile u
    // (global n-tile index t = u + 2i; phys col base = 32w + 8t)
    float frag[2][8][4];
#pragma unroll
    for (int i = 0; i < 2; ++i)
#pragma unroll
        for (int u = 0; u < 8; ++u)
#pragma unroll
            for (int c4 = 0; c4 < 4; ++c4) frag[i][u][c4] = 0.0f;

    // prologue: stages 0..2 in flight
    issue(0); CP_COMMIT();
    issue(1); CP_COMMIT();
    issue(2); CP_COMMIT();

    for (int k = 0; k < NCH; ++k) {
        if (k <= NCH - 3)      CP_WAIT(2);
        else if (k == NCH - 2) CP_WAIT(1);
        else                   CP_WAIT(0);
        __syncthreads();

        const int st = k & (NSTG - 1);
        const uint32_t* s1q = (const uint32_t*)(smf + st * STAGE_W);
        const uint32_t* s2q = s1q + CK * S1S;

        // A fragments for both m-tiles (conflict-free: strides %32==8)
        uint32_t A[2][4];
#pragma unroll
        for (int i = 0; i < 2; ++i) {
            const int cb = xw + 16 * i;
            A[i][0] = cvt_tf32(s1q[tig * S1S + cb + gid]);
            A[i][1] = cvt_tf32(s1q[tig * S1S + cb + gid + 8]);
            A[i][2] = cvt_tf32(s1q[(tig + 4) * S1S + cb + gid]);
            A[i][3] = cvt_tf32(s1q[(tig + 4) * S1S + cb + gid + 8]);
        }
        // B fragments: global tiles t = 0..9, phys base 32w + 8t
        uint32_t Bf[10][2];
#pragma unroll
        for (int t = 0; t < 10; ++t) {
            const int nb = xw + 8 * t + gid;
            Bf[t][0] = cvt_tf32(s2q[tig * S2S + nb]);
            Bf[t][1] = cvt_tf32(s2q[(tig + 4) * S2S + nb]);
        }
#pragma unroll
        for (int u = 0; u < 8; ++u) {
            mma_tf32(frag[0][u], A[0], Bf[u][0],     Bf[u][1]);
            mma_tf32(frag[1][u], A[1], Bf[u + 2][0], Bf[u + 2][1]);
        }

        // refill the stage that was consumed at iter k-1 (safe: top-of-iter
        // syncthreads guarantees all warps finished compute(k-1))
        if (k + 3 < NCH) issue(k + 3);
        CP_COMMIT();
    }

    // ---- epilogue: all smem reads done; alias stages as [d][x] staging
    __syncthreads();
    // reg c4: r = gid + 8*(c4>=2), cc = 2*tig + (c4&1)
    // x = 32w + 16i + r ; d = 8u + cc - r - 1  (same for both i!)
#pragma unroll
    for (int i = 0; i < 2; ++i)
#pragma unroll
        for (int u = 0; u < 8; ++u)
#pragma unroll
            for (int c4 = 0; c4 < 4; ++c4) {
                const int r  = gid + ((c4 >= 2) ? 8 : 0);
                const int cc = 2 * tig + (c4 & 1);
                const int d  = 8 * u + cc - r - 1;
                if (d >= 0 && d < D_)
                    smf[d * STG_S + xw + 16 * i + r] = lrelu(frag[i][u][c4]);
            }
    __syncthreads();

    // staging -> out[b, d, y, :], float4 coalesced: 3072 quads / 256 thr
    float* ob = out + ((b * D_) * H_ + y) * W_;
#pragma unroll
    for (int s = 0; s < 12; ++s) {
        const int qid = tid + s * NT;          // 0..3071
        const int d   = qid >> 6;              // 0..47
        const int xq  = (qid & 63) * 4;        // 0..252
        float4 v = *(const float4*)(smf + d * STG_S + xq);
        *(float4*)(ob + d * HW_ + xq) = v;
    }
}

extern "C" void kernel_launch(void* const* d_in, const int* in_sizes, int n_in,
                              void* d_out, int out_size) {
    (void)in_sizes; (void)n_in; (void)out_size;
    const float* f1 = (const float*)d_in[0];
    const float* f2 = (const float*)d_in[1];
    float* out = (float*)d_out;

    cudaFuncSetAttribute(corr1d_tc, cudaFuncAttributeMaxDynamicSharedMemorySize,
                         SMEM_BYTES);
    corr1d_tc<<<B_ * H_, NT, SMEM_BYTES>>>(f1, f2, out);
}

// round 9
// speedup vs baseline: 6.7044x; 1.0050x over previous
#include <cuda_runtime.h>
#include <cstdint>

// Correlation1dCost: feat [B,C,H,W] f32 -> out [B,D,H,W] f32
// out[b,d,y,x] = leakyrelu_0.1( sum_c f1[b,c,y,x] * f2[b,c,y,x+d-47] ), zero OOB
// Band-GEMM on tensor cores (m16n8k8 tf32), cp.async 3-stage rotating pipeline.
#define B_ 8
#define C_ 128
#define H_ 128
#define W_ 256
#define D_ 48
#define HW_ (H_ * W_)

#define CK 16              // channels per chunk = two k8 MMA steps
#define NCH 8              // chunks
#define NSTG 3             // pipeline stages
#define S1S 264            // s1 row stride (words), %32==8 -> conflict-free frags
#define S2S 328            // s2 row stride (words), %32==8
#define S2OFF 48           // left zero pad: phys col = x' + 48
#define NT 256             // 8 warps; warp w = x-rows [32w, 32w+32)
#define STG_S 260          // epilogue staging row stride

#define STAGE_W (CK * S1S + CK * S2S)          // 9472 words per stage
#define SMEM_BYTES (NSTG * STAGE_W * 4)        // 113664 B -> 2 CTAs/SM

extern __shared__ float smf[];

#define CP16(dst, src) asm volatile( \
    "cp.async.cg.shared.global [%0], [%1], 16;\n" :: "r"(dst), "l"(src))
#define CP_COMMIT() asm volatile("cp.async.commit_group;\n" ::: "memory")
#define CP_WAIT(n)  asm volatile("cp.async.wait_group %0;\n" :: "n"(n) : "memory")

__device__ __forceinline__ uint32_t cvt_tf32(uint32_t f) {
    uint32_t u;
    asm("cvt.rna.tf32.f32 %0, %1;" : "=r"(u) : "r"(f));
    return u;
}

__device__ __forceinline__ void mma_tf32(float d[4], const uint32_t a[4],
                                         uint32_t b0, uint32_t b1) {
    asm volatile(
        "mma.sync.aligned.m16n8k8.row.col.f32.tf32.tf32.f32 "
        "{%0,%1,%2,%3}, {%4,%5,%6,%7}, {%8,%9}, {%0,%1,%2,%3};"
        : "+f"(d[0]), "+f"(d[1]), "+f"(d[2]), "+f"(d[3])
        : "r"(a[0]), "r"(a[1]), "r"(a[2]), "r"(a[3]), "r"(b0), "r"(b1));
}

__device__ __forceinline__ float lrelu(float v) { return fmaxf(v, 0.1f * v); }

__global__ __launch_bounds__(NT, 2)
void corr1d_tc(const float* __restrict__ f1,
               const float* __restrict__ f2,
               float* __restrict__ out) {
    const int tid  = threadIdx.x;
    const int b    = blockIdx.x >> 7;          // blockIdx.x = b*H + y
    const int y    = blockIdx.x & (H_ - 1);
    const int lane = tid & 31;
    const int w    = tid >> 5;                 // warp 0..7 -> x in [32w, 32w+32)
    const int gid  = lane >> 2;                // 0..7
    const int tig  = lane & 3;                 // 0..3
    const int xw   = 32 * w;

    const float* f1p = f1 + (b * C_ * H_ + y) * W_;
    const float* f2p = f2 + (b * C_ * H_ + y) * W_;

    // zero s2 left pads for all stages ONCE (cp.async fills never touch them)
    for (int i = tid; i < NSTG * CK * S2OFF; i += NT) {
        int st = i / (CK * S2OFF);
        int r  = i % (CK * S2OFF);
        smf[st * STAGE_W + CK * S1S + (r / S2OFF) * S2S + (r % S2OFF)] = 0.0f;
    }

    // fill geometry: per chunk per tensor: 16 rows x 256 cols = 1024 quads
    // thread handles rows qr, qr+4, qr+8, qr+12 at quad col qc
    const int qr = tid >> 6;                   // 0..3
    const int qc = (tid & 63) * 4;             // 0..252
    const uint32_t smem_base = (uint32_t)__cvta_generic_to_shared(smf);

    auto issue = [&](int k) {
        const int st = k % NSTG;
        const int c0 = k * CK;
        const uint32_t s1b = smem_base + (st * STAGE_W) * 4;
        const uint32_t s2b = s1b + (CK * S1S) * 4;
#pragma unroll
        for (int j = 0; j < 4; ++j) {
            const int r = qr + 4 * j;
            CP16(s1b + (r * S1S + qc) * 4,         f1p + (c0 + r) * HW_ + qc);
            CP16(s2b + (r * S2S + S2OFF + qc) * 4, f2p + (c0 + r) * HW_ + qc);
        }
    };

    // D fragments: frag[i][u] = m-tile i (x base 32w+16i), band tile u
    // (global n-tile t = u + 2i; phys col base = 32w + 8t)
    float frag[2][8][4];
#pragma unroll
    for (int i = 0; i < 2; ++i)
#pragma unroll
        for (int u = 0; u < 8; ++u)
#pragma unroll
            for (int c4 = 0; c4 < 4; ++c4) frag[i][u][c4] = 0.0f;

    // prologue: 2 chunks in flight
    issue(0); CP_COMMIT();
    issue(1); CP_COMMIT();

    for (int k = 0; k < NCH; ++k) {
        if (k < NCH - 1) CP_WAIT(1); else CP_WAIT(0);
        __syncthreads();                       // stage k fully visible to all

        // refill: stage (k+2)%3 == (k-1)%3, sealed by the barrier above
        if (k + 2 < NCH) { issue(k + 2); CP_COMMIT(); }

        const int st = k % NSTG;
        const uint32_t* s1q = (const uint32_t*)(smf + st * STAGE_W);
        const uint32_t* s2q = s1q + CK * S1S;

#pragma unroll
        for (int ks = 0; ks < 2; ++ks) {
            const int kr = ks * 8;
            // A fragments for both m-tiles (conflict-free: strides %32==8)
            uint32_t A[2][4];
#pragma unroll
            for (int i = 0; i < 2; ++i) {
                const int cb = xw + 16 * i;
                A[i][0] = cvt_tf32(s1q[(kr + tig) * S1S + cb + gid]);
                A[i][1] = cvt_tf32(s1q[(kr + tig) * S1S + cb + gid + 8]);
                A[i][2] = cvt_tf32(s1q[(kr + tig + 4) * S1S + cb + gid]);
                A[i][3] = cvt_tf32(s1q[(kr + tig + 4) * S1S + cb + gid + 8]);
            }
            // B fragments: global tiles t = 0..9, phys base 32w + 8t
            uint32_t Bf[10][2];
#pragma unroll
            for (int t = 0; t < 10; ++t) {
                const int nb = xw + 8 * t + gid;
                Bf[t][0] = cvt_tf32(s2q[(kr + tig) * S2S + nb]);
                Bf[t][1] = cvt_tf32(s2q[(kr + tig + 4) * S2S + nb]);
            }
#pragma unroll
            for (int u = 0; u < 8; ++u) {
                mma_tf32(frag[0][u], A[0], Bf[u][0],     Bf[u][1]);
                mma_tf32(frag[1][u], A[1], Bf[u + 2][0], Bf[u + 2][1]);
            }
        }
    }

    // ---- epilogue: all smem reads done; alias stages as [d][x] staging
    __syncthreads();
    // reg c4: r = gid + 8*(c4>=2), cc = 2*tig + (c4&1)
    // x = 32w + 16i + r ; d = 8u + cc - r - 1  (same for both i)
#pragma unroll
    for (int i = 0; i < 2; ++i)
#pragma unroll
        for (int u = 0; u < 8; ++u)
#pragma unroll
            for (int c4 = 0; c4 < 4; ++c4) {
                const int r  = gid + ((c4 >= 2) ? 8 : 0);
                const int cc = 2 * tig + (c4 & 1);
                const int d  = 8 * u + cc - r - 1;
                if (d >= 0 && d < D_)
                    smf[d * STG_S + xw + 16 * i + r] = lrelu(frag[i][u][c4]);
            }
    __syncthreads();

    // staging -> out[b, d, y, :], float4 coalesced: 3072 quads / 256 thr
    float* ob = out + ((b * D_) * H_ + y) * W_;
#pragma unroll
    for (int s = 0; s < 12; ++s) {
        const int qid = tid + s * NT;          // 0..3071
        const int d   = qid >> 6;              // 0..47
        const int xq  = (qid & 63) * 4;        // 0..252
        float4 v = *(const float4*)(smf + d * STG_S + xq);
        *(float4*)(ob + d * HW_ + xq) = v;
    }
}

extern "C" void kernel_launch(void* const* d_in, const int* in_sizes, int n_in,
                              void* d_out, int out_size) {
    (void)in_sizes; (void)n_in; (void)out_size;
    const float* f1 = (const float*)d_in[0];
    const float* f2 = (const float*)d_in[1];
    float* out = (float*)d_out;

    cudaFuncSetAttribute(corr1d_tc, cudaFuncAttributeMaxDynamicSharedMemorySize,
                         SMEM_BYTES);
    corr1d_tc<<<B_ * H_, NT, SMEM_BYTES>>>(f1, f2, out);
}

// round 10
// speedup vs baseline: 6.9802x; 1.0411x over previous
#include <cuda_runtime.h>
#include <cstdint>

// Correlation1dCost: feat [B,C,H,W] f32 -> out [B,D,H,W] f32
// out[b,d,y,x] = leakyrelu_0.1( sum_c f1[b,c,y,x] * f2[b,c,y,x+d-47] ), zero OOB
// Band-GEMM on tensor cores (m16n8k8 tf32), cp.async 3-stage rotating pipeline.
// Raw fp32 bits fed to HMMA.tf32 (hardware truncates to tf32 = RZ): no CVTs.
#define B_ 8
#define C_ 128
#define H_ 128
#define W_ 256
#define D_ 48
#define HW_ (H_ * W_)

#define CK 16              // channels per chunk = two k8 MMA steps
#define NCH 8              // chunks
#define NSTG 3             // pipeline stages
#define S1S 264            // s1 row stride (words), %32==8 -> conflict-free frags
#define S2S 328            // s2 row stride (words), %32==8
#define S2OFF 48           // left zero pad: phys col = x' + 48
#define NT 256             // 8 warps; warp w = x-rows [32w, 32w+32)
#define STG_S 260          // epilogue staging row stride

#define STAGE_W (CK * S1S + CK * S2S)          // 9472 words per stage
#define SMEM_BYTES (NSTG * STAGE_W * 4)        // 113664 B -> 2 CTAs/SM

extern __shared__ float smf[];

#define CP16(dst, src) asm volatile( \
    "cp.async.cg.shared.global [%0], [%1], 16;\n" :: "r"(dst), "l"(src))
#define CP_COMMIT() asm volatile("cp.async.commit_group;\n" ::: "memory")
#define CP_WAIT(n)  asm volatile("cp.async.wait_group %0;\n" :: "n"(n) : "memory")

__device__ __forceinline__ void mma_tf32(float d[4], const uint32_t a[4],
                                         uint32_t b0, uint32_t b1) {
    asm volatile(
        "mma.sync.aligned.m16n8k8.row.col.f32.tf32.tf32.f32 "
        "{%0,%1,%2,%3}, {%4,%5,%6,%7}, {%8,%9}, {%0,%1,%2,%3};"
        : "+f"(d[0]), "+f"(d[1]), "+f"(d[2]), "+f"(d[3])
        : "r"(a[0]), "r"(a[1]), "r"(a[2]), "r"(a[3]), "r"(b0), "r"(b1));
}

__device__ __forceinline__ float lrelu(float v) { return fmaxf(v, 0.1f * v); }

__global__ __launch_bounds__(NT, 2)
void corr1d_tc(const float* __restrict__ f1,
               const float* __restrict__ f2,
               float* __restrict__ out) {
    const int tid  = threadIdx.x;
    const int b    = blockIdx.x >> 7;          // blockIdx.x = b*H + y
    const int y    = blockIdx.x & (H_ - 1);
    const int lane = tid & 31;
    const int w    = tid >> 5;                 // warp 0..7 -> x in [32w, 32w+32)
    const int gid  = lane >> 2;                // 0..7
    const int tig  = lane & 3;                 // 0..3
    const int xw   = 32 * w;

    const float* f1p = f1 + (b * C_ * H_ + y) * W_;
    const float* f2p = f2 + (b * C_ * H_ + y) * W_;

    // zero s2 left pads for all stages ONCE (cp.async fills never touch them)
    for (int i = tid; i < NSTG * CK * S2OFF; i += NT) {
        int st = i / (CK * S2OFF);
        int r  = i % (CK * S2OFF);
        smf[st * STAGE_W + CK * S1S + (r / S2OFF) * S2S + (r % S2OFF)] = 0.0f;
    }

    // fill geometry: per chunk per tensor: 16 rows x 256 cols = 1024 quads
    const int qr = tid >> 6;                   // 0..3
    const int qc = (tid & 63) * 4;             // 0..252
    const uint32_t smem_base = (uint32_t)__cvta_generic_to_shared(smf);

    auto issue = [&](int k, int st) {
        const int c0 = k * CK;
        const uint32_t s1b = smem_base + (st * STAGE_W) * 4;
        const uint32_t s2b = s1b + (CK * S1S) * 4;
#pragma unroll
        for (int j = 0; j < 4; ++j) {
            const int r = qr + 4 * j;
            CP16(s1b + (r * S1S + qc) * 4,         f1p + (c0 + r) * HW_ + qc);
            CP16(s2b + (r * S2S + S2OFF + qc) * 4, f2p + (c0 + r) * HW_ + qc);
        }
    };

    // D fragments: frag[i][u] = m-tile i (x base 32w+16i), band tile u
    float frag[2][8][4];
#pragma unroll
    for (int i = 0; i < 2; ++i)
#pragma unroll
        for (int u = 0; u < 8; ++u)
#pragma unroll
            for (int c4 = 0; c4 < 4; ++c4) frag[i][u][c4] = 0.0f;

    // prologue: 2 chunks in flight
    issue(0, 0); CP_COMMIT();
    issue(1, 1); CP_COMMIT();

    // hoisted per-warp fragment base offsets (words)
    const int a_row = tig * S1S;               // + kr*S1S per k-step
    const int b_row = tig * S2S;
    int st = 0, st_n = 2;                      // consume stage, next-issue stage

    for (int k = 0; k < NCH; ++k) {
        if (k < NCH - 1) CP_WAIT(1); else CP_WAIT(0);
        __syncthreads();                       // stage k fully visible to all

        if (k + 2 < NCH) {
            issue(k + 2, st_n); CP_COMMIT();
            if (++st_n == NSTG) st_n = 0;
        }

        const uint32_t* s1q = (const uint32_t*)(smf + st * STAGE_W);
        const uint32_t* s2q = s1q + CK * S1S;
        if (++st == NSTG) st = 0;

#pragma unroll
        for (int ks = 0; ks < 2; ++ks) {
            const uint32_t* s1r = s1q + (ks * 8) * S1S + a_row + xw + gid;
            const uint32_t* s2r = s2q + (ks * 8) * S2S + b_row + xw + gid;

            // A fragments, both m-tiles (raw fp32 bits; HMMA truncates to tf32)
            uint32_t A[2][4];
#pragma unroll
            for (int i = 0; i < 2; ++i) {
                A[i][0] = s1r[16 * i];
                A[i][1] = s1r[16 * i + 8];
                A[i][2] = s1r[4 * S1S + 16 * i];
                A[i][3] = s1r[4 * S1S + 16 * i + 8];
            }
            // B fragments: global tiles t = 0..9, phys base 32w + 8t
            uint32_t Bf[10][2];
#pragma unroll
            for (int t = 0; t < 10; ++t) {
                Bf[t][0] = s2r[8 * t];
                Bf[t][1] = s2r[4 * S2S + 8 * t];
            }
#pragma unroll
            for (int u = 0; u < 8; ++u) {
                mma_tf32(frag[0][u], A[0], Bf[u][0],     Bf[u][1]);
                mma_tf32(frag[1][u], A[1], Bf[u + 2][0], Bf[u + 2][1]);
            }
        }
    }

    // ---- epilogue: all smem reads done; alias stages as [d][x] staging
    __syncthreads();
    // reg c4: r = gid + 8*(c4>=2), cc = 2*tig + (c4&1)
    // x = 32w + 16i + r ; d = 8u + cc - r - 1  (same for both i)
#pragma unroll
    for (int i = 0; i < 2; ++i)
#pragma unroll
        for (int u = 0; u < 8; ++u)
#pragma unroll
            for (int c4 = 0; c4 < 4; ++c4) {
                const int r  = gid + ((c4 >= 2) ? 8 : 0);
                const int cc = 2 * tig + (c4 & 1);
                const int d  = 8 * u + cc - r - 1;
                if (d >= 0 && d < D_)
                    smf[d * STG_S + xw + 16 * i + r] = lrelu(frag[i][u][c4]);
            }
    __syncthreads();

    // staging -> out[b, d, y, :], float4 coalesced: 3072 quads / 256 thr
    float* ob = out + ((b * D_) * H_ + y) * W_;
#pragma unroll
    for (int s = 0; s < 12; ++s) {
        const int qid = tid + s * NT;          // 0..3071
        const int d   = qid >> 6;              // 0..47
        const int xq  = (qid & 63) * 4;        // 0..252
        float4 v = *(const float4*)(smf + d * STG_S + xq);
        *(float4*)(ob + d * HW_ + xq) = v;
    }
}

extern "C" void kernel_launch(void* const* d_in, const int* in_sizes, int n_in,
                              void* d_out, int out_size) {
    (void)in_sizes; (void)n_in; (void)out_size;
    const float* f1 = (const float*)d_in[0];
    const float* f2 = (const float*)d_in[1];
    float* out = (float*)d_out;

    cudaFuncSetAttribute(corr1d_tc, cudaFuncAttributeMaxDynamicSharedMemorySize,
                         SMEM_BYTES);
    corr1d_tc<<<B_ * H_, NT, SMEM_BYTES>>>(f1, f2, out);
}